// round 8
// baseline (speedup 1.0000x reference)
#include <cuda_runtime.h>
#include <cstdint>
#include <cstddef>

// Problem dims
#define B_  512
#define S_  1024
#define I_  64
#define H_  128
#define G_  384   // 3*H
#define C_  10

// Scratch (device globals: allocation APIs are forbidden)
// g_xg layout: INTERLEAVED [b/4][s][g][4] so one CTA's 4 batch rows for a
// given (s, gate) are 16 contiguous bytes -> single cp.async.16B per step.
__device__ float g_xg[(size_t)B_ * S_ * G_];
__device__ float g_h1[(size_t)B_ * S_ * H_];    // layer0 hidden outputs [b][s][h]
__device__ float g_h2last[B_ * H_];             // last hidden of layer1

typedef unsigned long long u64;

__device__ __forceinline__ u64 pk2(float lo, float hi) {
    u64 r; asm("mov.b64 %0, {%1, %2};" : "=l"(r) : "f"(lo), "f"(hi)); return r;
}
__device__ __forceinline__ void upk2(u64 v, float& lo, float& hi) {
    asm("mov.b64 {%0, %1}, %2;" : "=f"(lo), "=f"(hi) : "l"(v));
}
__device__ __forceinline__ void fma2(u64& d, u64 a, u64 b) {
    asm("fma.rn.f32x2 %0, %1, %2, %0;" : "+l"(d) : "l"(a), "l"(b));
}

// MUFU.TANH — single-op tanh (sm_75+)
__device__ __forceinline__ float tanh_ap(float x) {
    float y; asm("tanh.approx.f32 %0, %1;" : "=f"(y) : "f"(x)); return y;
}
__device__ __forceinline__ float sig_ap(float x) {
    return fmaf(tanh_ap(0.5f * x), 0.5f, 0.5f);
}

__device__ __forceinline__ uint32_t smem_u32(const void* p) {
    uint32_t a;
    asm("{ .reg .u64 t; cvta.to.shared.u64 t, %1; cvt.u32.u64 %0, t; }"
        : "=r"(a) : "l"(p));
    return a;
}
// Predicated 16-byte cp.async (.cg: bypass L1, xg is read exactly once)
__device__ __forceinline__ void cp_async16(uint32_t dst, const float* src, int pred) {
    asm volatile(
        "{\n\t.reg .pred p;\n\tsetp.ne.u32 p, %2, 0;\n\t"
        "@p cp.async.cg.shared.global [%0], [%1], 16;\n\t}"
        :: "r"(dst), "l"(src), "r"(pred) : "memory");
}
__device__ __forceinline__ void cp_commit() {
    asm volatile("cp.async.commit_group;" ::: "memory");
}
__device__ __forceinline__ void cp_wait1() {
    asm volatile("cp.async.wait_group 1;" ::: "memory");
}

// ============================================================================
// Phase 1/3: xg = A @ W^T + bias, output in interleaved layout
//   element (b, s, g) -> g_xg[(((b>>2)*S + s)*G + g)*4 + (b&3)]
// A tile = 64 consecutive m = b*S+s rows; 64 | S so each tile has ONE b.
// Persistent CTAs; W k-major in smem; fp32x2 FMA; 256 threads; A prefetch.
// ============================================================================
template<int K, bool A_IS_H1>
__global__ __launch_bounds__(256) void gemm_xg_kernel(
    const float* __restrict__ Ain, const float* __restrict__ W,
    const float* __restrict__ bias, int ntiles)
{
    extern __shared__ float smem[];
    float* Ws = smem;              // [K][384], k-major
    float* As = smem + K * G_;     // [64][K]
    const float* A = A_IS_H1 ? g_h1 : Ain;

    const int tid = threadIdx.x;
    constexpr int PF = (64 * K / 4) / 256;

    for (int idx = tid; idx < G_ * (K / 4); idx += 256) {
        int kq = idx / G_;
        int g  = idx - kq * G_;
        float4 w4 = *reinterpret_cast<const float4*>(W + (size_t)g * K + 4 * kq);
        Ws[(4 * kq + 0) * G_ + g] = w4.x;
        Ws[(4 * kq + 1) * G_ + g] = w4.y;
        Ws[(4 * kq + 2) * G_ + g] = w4.z;
        Ws[(4 * kq + 3) * G_ + g] = w4.w;
    }

    const int cg = tid & 31;
    const int rg = tid >> 5;

    float4 bv[3];
#pragma unroll
    for (int gg = 0; gg < 3; ++gg)
        bv[gg] = *reinterpret_cast<const float4*>(bias + gg * H_ + 4 * cg);

    int tile = blockIdx.x;
    float4 pf[PF];
    if (tile < ntiles) {
        const float4* Ab = reinterpret_cast<const float4*>(A + (size_t)tile * 64 * K);
#pragma unroll
        for (int i = 0; i < PF; ++i) pf[i] = Ab[tid + 256 * i];
    }
    __syncthreads();

    for (; tile < ntiles; tile += gridDim.x) {
#pragma unroll
        for (int i = 0; i < PF; ++i)
            reinterpret_cast<float4*>(As)[tid + 256 * i] = pf[i];
        __syncthreads();

        int ntile = tile + gridDim.x;
        if (ntile < ntiles) {
            const float4* Ab = reinterpret_cast<const float4*>(A + (size_t)ntile * 64 * K);
#pragma unroll
            for (int i = 0; i < PF; ++i) pf[i] = Ab[tid + 256 * i];
        }

        u64 acc[8][3][2];
#pragma unroll
        for (int r = 0; r < 8; ++r)
#pragma unroll
            for (int gg = 0; gg < 3; ++gg) {
                acc[r][gg][0] = 0ull;
                acc[r][gg][1] = 0ull;
            }

#pragma unroll 2
        for (int k4 = 0; k4 < K; k4 += 4) {
            float4 af[8];
#pragma unroll
            for (int r = 0; r < 8; ++r)
                af[r] = *reinterpret_cast<const float4*>(&As[(rg * 8 + r) * K + k4]);
#pragma unroll
            for (int kk = 0; kk < 4; ++kk) {
                ulonglong2 wp[3];
#pragma unroll
                for (int gg = 0; gg < 3; ++gg)
                    wp[gg] = *reinterpret_cast<const ulonglong2*>(
                        &Ws[(size_t)(k4 + kk) * G_ + gg * H_ + 4 * cg]);
#pragma unroll
                for (int r = 0; r < 8; ++r) {
                    float a = (kk == 0) ? af[r].x : (kk == 1) ? af[r].y
                            : (kk == 2) ? af[r].z : af[r].w;
                    u64 ad = pk2(a, a);
#pragma unroll
                    for (int gg = 0; gg < 3; ++gg) {
                        fma2(acc[r][gg][0], ad, wp[gg].x);
                        fma2(acc[r][gg][1], ad, wp[gg].y);
                    }
                }
            }
        }

        // Interleaved store: one b per tile
        const int b    = tile >> 4;          // 16 s-tiles per b
        const int lane = b & 3;
        const int s0   = (tile & 15) * 64;
        float* Cb = g_xg + ((size_t)(b >> 2) * S_ + s0) * (G_ * 4) + lane;
#pragma unroll
        for (int r = 0; r < 8; ++r) {
            float* Crow = Cb + (size_t)(rg * 8 + r) * (G_ * 4);
#pragma unroll
            for (int gg = 0; gg < 3; ++gg) {
                float x0, x1, x2, x3;
                upk2(acc[r][gg][0], x0, x1);
                upk2(acc[r][gg][1], x2, x3);
                float* p = Crow + (gg * H_ + 4 * cg) * 4;
                p[0]  = x0 + bv[gg].x;
                p[4]  = x1 + bv[gg].y;
                p[8]  = x2 + bv[gg].z;
                p[12] = x3 + bv[gg].w;
            }
        }
        __syncthreads();
    }
}

// ============================================================================
// Phase 2/4: recurrent scan. 128 CTAs x 4 batch rows, 384 threads.
// Thread g owns gate column g; W_hh column as 64 packed u64 k-pairs in regs.
// xg staged one step ahead via ONE cp.async.16B per thread (interleaved xg).
// sec2 keeps old-h in registers (no re-read).
// ============================================================================
template<bool WRITE_ALL>
__global__ __launch_bounds__(384, 1) void gru_rec_kernel(
    const float* __restrict__ Whh, const float* __restrict__ bhh)
{
    __shared__ float h_s[4][H_];
    __shared__ float4 rbuf[H_];
    __shared__ float4 zbuf[H_];
    __shared__ float4 xstage[2][G_];

    const int g  = threadIdx.x;
    const int rb = blockIdx.x * 4;

    u64 wp[64];
    const u64* wrow = reinterpret_cast<const u64*>(Whh + (size_t)g * H_);
#pragma unroll
    for (int kk = 0; kk < 64; ++kk) wp[kk] = wrow[kk];
    const float bh = bhh[g];

    for (int idx = g; idx < 4 * H_; idx += 384)
        (&h_s[0][0])[idx] = 0.f;
    __syncthreads();

    const int sec = g >> 7;
    const int j   = g & 127;

    // interleaved xg: row = [bg=blockIdx][t][g][0..3]
    const float* xp = g_xg + (size_t)blockIdx.x * S_ * (G_ * 4) + g * 4;
    float* hall = g_h1 + ((size_t)rb * S_) * H_ + j;

    const uint32_t xs0 = smem_u32(&xstage[0][g]);
    const uint32_t xs1 = smem_u32(&xstage[1][g]);

    // Prologue: stage t=0
    cp_async16(xs0, xp, 1);
    cp_commit();
    xp += G_ * 4;

    // sec2's private copy of old h (it is the sole writer of h_s)
    float hp0 = 0.f, hp1 = 0.f, hp2 = 0.f, hp3 = 0.f;

    const ulonglong2* hr0 = reinterpret_cast<const ulonglong2*>(h_s[0]);
    const ulonglong2* hr1 = reinterpret_cast<const ulonglong2*>(h_s[1]);
    const ulonglong2* hr2 = reinterpret_cast<const ulonglong2*>(h_s[2]);
    const ulonglong2* hr3 = reinterpret_cast<const ulonglong2*>(h_s[3]);

    for (int t = 0; t < S_; ++t) {
        // Stage t+1 (issue pinned here, a full step before use)
        cp_async16((t & 1) ? xs0 : xs1, xp, t + 1 < S_);
        cp_commit();
        xp += G_ * 4;

        // -------- dot: h(t-1) . w for 4 rows --------
        u64 a0 = 0ull, a1 = 0ull, a2 = 0ull, a3 = 0ull;
#pragma unroll
        for (int kk = 0; kk < 32; ++kk) {
            ulonglong2 h0 = hr0[kk];
            ulonglong2 h1 = hr1[kk];
            ulonglong2 h2 = hr2[kk];
            ulonglong2 h3 = hr3[kk];
            u64 w0 = wp[2 * kk];
            u64 w1 = wp[2 * kk + 1];
            fma2(a0, h0.x, w0);
            fma2(a1, h1.x, w0);
            fma2(a2, h2.x, w0);
            fma2(a3, h3.x, w0);
            fma2(a0, h0.y, w1);
            fma2(a1, h1.y, w1);
            fma2(a2, h2.y, w1);
            fma2(a3, h3.y, w1);
        }
        float g0, g1, g2, g3, tlo, thi;
        upk2(a0, tlo, thi); g0 = tlo + thi + bh;
        upk2(a1, tlo, thi); g1 = tlo + thi + bh;
        upk2(a2, tlo, thi); g2 = tlo + thi + bh;
        upk2(a3, tlo, thi); g3 = tlo + thi + bh;

        cp_wait1();
        float4 xv = (t & 1) ? xstage[1][g] : xstage[0][g];

        if (sec == 0) {
            rbuf[j] = make_float4(sig_ap(xv.x + g0), sig_ap(xv.y + g1),
                                  sig_ap(xv.z + g2), sig_ap(xv.w + g3));
        } else if (sec == 1) {
            zbuf[j] = make_float4(sig_ap(xv.x + g0), sig_ap(xv.y + g1),
                                  sig_ap(xv.z + g2), sig_ap(xv.w + g3));
        }
        __syncthreads();
        if (sec == 2) {
            float4 rr = rbuf[j];
            float4 zz = zbuf[j];
            float n0 = tanh_ap(fmaf(rr.x, g0, xv.x));
            float n1 = tanh_ap(fmaf(rr.y, g1, xv.y));
            float n2 = tanh_ap(fmaf(rr.z, g2, xv.z));
            float n3 = tanh_ap(fmaf(rr.w, g3, xv.w));
            hp0 = fmaf(zz.x, hp0 - n0, n0);
            hp1 = fmaf(zz.y, hp1 - n1, n1);
            hp2 = fmaf(zz.z, hp2 - n2, n2);
            hp3 = fmaf(zz.w, hp3 - n3, n3);
            h_s[0][j] = hp0;
            h_s[1][j] = hp1;
            h_s[2][j] = hp2;
            h_s[3][j] = hp3;
            if (WRITE_ALL) {
                hall[0]                        = hp0;
                hall[(size_t)S_ * H_]          = hp1;
                hall[2 * (size_t)S_ * H_]      = hp2;
                hall[3 * (size_t)S_ * H_]      = hp3;
            } else if (t == S_ - 1) {
                g_h2last[(rb + 0) * H_ + j] = hp0;
                g_h2last[(rb + 1) * H_ + j] = hp1;
                g_h2last[(rb + 2) * H_ + j] = hp2;
                g_h2last[(rb + 3) * H_ + j] = hp3;
            }
        }
        __syncthreads();
        if (WRITE_ALL) hall += H_;
    }
}

// ============================================================================
// Phase 5: out[b][c] = h2last[b] . fc_w[c] + fc_b[c]
// ============================================================================
__global__ __launch_bounds__(128) void fc_kernel(
    const float* __restrict__ fw, const float* __restrict__ fb,
    float* __restrict__ out)
{
    __shared__ float sh[H_];
    const int b = blockIdx.x;
    sh[threadIdx.x] = g_h2last[b * H_ + threadIdx.x];
    __syncthreads();
    if (threadIdx.x < C_) {
        const int c = threadIdx.x;
        float acc = fb[c];
#pragma unroll
        for (int jj = 0; jj < H_; ++jj)
            acc += sh[jj] * fw[c * H_ + jj];
        out[b * C_ + c] = acc;
    }
}

extern "C" void kernel_launch(void* const* d_in, const int* in_sizes, int n_in,
                              void* d_out, int out_size)
{
    (void)in_sizes; (void)n_in; (void)out_size;
    const float* x      = (const float*)d_in[0];
    const float* W_ih0  = (const float*)d_in[1];
    const float* W_hh0  = (const float*)d_in[2];
    const float* b_ih0  = (const float*)d_in[3];
    const float* b_hh0  = (const float*)d_in[4];
    const float* W_ih1  = (const float*)d_in[5];
    const float* W_hh1  = (const float*)d_in[6];
    const float* b_ih1  = (const float*)d_in[7];
    const float* b_hh1  = (const float*)d_in[8];
    const float* fc_w   = (const float*)d_in[9];
    const float* fc_b   = (const float*)d_in[10];
    float* out = (float*)d_out;

    const int ntiles = (B_ * S_) / 64;   // 8192
    const int smem64  = 64  * 4 * (G_ + 64);   // 114688 B
    const int smem128 = 128 * 4 * (G_ + 64);   // 229376 B

    cudaFuncSetAttribute(gemm_xg_kernel<64, false>,
                         cudaFuncAttributeMaxDynamicSharedMemorySize, smem64);
    cudaFuncSetAttribute(gemm_xg_kernel<128, true>,
                         cudaFuncAttributeMaxDynamicSharedMemorySize, smem128);

    // Layer 0
    gemm_xg_kernel<64, false><<<148, 256, smem64>>>(x, W_ih0, b_ih0, ntiles);
    gru_rec_kernel<true><<<128, 384>>>(W_hh0, b_hh0);
    // Layer 1
    gemm_xg_kernel<128, true><<<148, 256, smem128>>>(nullptr, W_ih1, b_ih1, ntiles);
    gru_rec_kernel<false><<<128, 384>>>(W_hh1, b_hh1);
    // Head
    fc_kernel<<<B_, 128>>>(fc_w, fc_b, out);
}

// round 9
// speedup vs baseline: 1.2237x; 1.2237x over previous
#include <cuda_runtime.h>
#include <cstdint>
#include <cstddef>

// Problem dims
#define B_  512
#define S_  1024
#define I_  64
#define H_  128
#define G_  384   // 3*H
#define C_  10

// Scratch (device globals: allocation APIs are forbidden)
// g_xg layout: INTERLEAVED [b/4][s][g][4] so one rec-CTA's 4 batch rows for a
// given (s, gate) are 16 contiguous bytes -> single cp.async.16B per step.
__device__ float g_xg[(size_t)B_ * S_ * G_];
__device__ float g_h1[(size_t)B_ * S_ * H_];    // layer0 hidden outputs [b][s][h]
__device__ float g_h2last[B_ * H_];             // last hidden of layer1

typedef unsigned long long u64;

__device__ __forceinline__ u64 pk2(float lo, float hi) {
    u64 r; asm("mov.b64 %0, {%1, %2};" : "=l"(r) : "f"(lo), "f"(hi)); return r;
}
__device__ __forceinline__ void upk2(u64 v, float& lo, float& hi) {
    asm("mov.b64 {%0, %1}, %2;" : "=f"(lo), "=f"(hi) : "l"(v));
}
__device__ __forceinline__ void fma2(u64& d, u64 a, u64 b) {
    asm("fma.rn.f32x2 %0, %1, %2, %0;" : "+l"(d) : "l"(a), "l"(b));
}

// MUFU.TANH — single-op tanh (sm_75+)
__device__ __forceinline__ float tanh_ap(float x) {
    float y; asm("tanh.approx.f32 %0, %1;" : "=f"(y) : "f"(x)); return y;
}
__device__ __forceinline__ float sig_ap(float x) {
    return fmaf(tanh_ap(0.5f * x), 0.5f, 0.5f);
}

__device__ __forceinline__ uint32_t smem_u32(const void* p) {
    uint32_t a;
    asm("{ .reg .u64 t; cvta.to.shared.u64 t, %1; cvt.u32.u64 %0, t; }"
        : "=r"(a) : "l"(p));
    return a;
}
// Predicated 16-byte cp.async (.cg: bypass L1, xg is read exactly once)
__device__ __forceinline__ void cp_async16(uint32_t dst, const float* src, int pred) {
    asm volatile(
        "{\n\t.reg .pred p;\n\tsetp.ne.u32 p, %2, 0;\n\t"
        "@p cp.async.cg.shared.global [%0], [%1], 16;\n\t}"
        :: "r"(dst), "l"(src), "r"(pred) : "memory");
}
__device__ __forceinline__ void cp_commit() {
    asm volatile("cp.async.commit_group;" ::: "memory");
}
__device__ __forceinline__ void cp_wait1() {
    asm volatile("cp.async.wait_group 1;" ::: "memory");
}

// ============================================================================
// Phase 1/3: xg = A @ W^T + bias, output in interleaved layout
//   element (b, s, g) -> g_xg[(((b>>2)*S + s)*G + g)*4 + (b&3)]
// Tile = 4 batches x 16 timesteps (64 rows): row r -> b = 4*bq + (r>>4),
// s = s0 + (r&15). Warp rg computes rows {rg + 8r}, so each thread holds all
// 4 b-lanes of (s, g) quads -> interleaved stores are single STG.128,
// fully coalesced across lanes (64B stride).
// ============================================================================
template<int K, bool A_IS_H1>
__global__ __launch_bounds__(256) void gemm_xg_kernel(
    const float* __restrict__ Ain, const float* __restrict__ W,
    const float* __restrict__ bias, int ntiles)
{
    extern __shared__ float smem[];
    float* Ws = smem;              // [K][384], k-major
    float* As = smem + K * G_;     // [64][K]
    const float* A = A_IS_H1 ? g_h1 : Ain;

    const int tid = threadIdx.x;
    constexpr int KQ = K / 4;                 // float4 per row
    constexpr int PF = (64 * KQ) / 256;       // float4 per thread per tile

    for (int idx = tid; idx < G_ * KQ; idx += 256) {
        int kq = idx / G_;
        int g  = idx - kq * G_;
        float4 w4 = *reinterpret_cast<const float4*>(W + (size_t)g * K + 4 * kq);
        Ws[(4 * kq + 0) * G_ + g] = w4.x;
        Ws[(4 * kq + 1) * G_ + g] = w4.y;
        Ws[(4 * kq + 2) * G_ + g] = w4.z;
        Ws[(4 * kq + 3) * G_ + g] = w4.w;
    }

    const int cg = tid & 31;
    const int rg = tid >> 5;

    float4 bv[3];
#pragma unroll
    for (int gg = 0; gg < 3; ++gg)
        bv[gg] = *reinterpret_cast<const float4*>(bias + gg * H_ + 4 * cg);

    // tile -> (bq, s0):  ntiles = (B/4) * (S/16)
    auto tile_src = [&](int tl, int i) -> const float4* {
        int idx = tid + 256 * i;
        int r   = idx / KQ;
        int c   = idx - r * KQ;
        int bq  = tl >> 6;
        int s0  = (tl & 63) << 4;
        size_t row = (size_t)(4 * bq + (r >> 4)) * S_ + s0 + (r & 15);
        return reinterpret_cast<const float4*>(A + row * K) + c;
    };

    int tile = blockIdx.x;
    float4 pf[PF];
    if (tile < ntiles) {
#pragma unroll
        for (int i = 0; i < PF; ++i) pf[i] = *tile_src(tile, i);
    }
    __syncthreads();

    for (; tile < ntiles; tile += gridDim.x) {
#pragma unroll
        for (int i = 0; i < PF; ++i)
            reinterpret_cast<float4*>(As)[tid + 256 * i] = pf[i];
        __syncthreads();

        int ntile = tile + gridDim.x;
        if (ntile < ntiles) {
#pragma unroll
            for (int i = 0; i < PF; ++i) pf[i] = *tile_src(ntile, i);
        }

        u64 acc[8][3][2];
#pragma unroll
        for (int r = 0; r < 8; ++r)
#pragma unroll
            for (int gg = 0; gg < 3; ++gg) {
                acc[r][gg][0] = 0ull;
                acc[r][gg][1] = 0ull;
            }

#pragma unroll 2
        for (int k4 = 0; k4 < K; k4 += 4) {
            float4 af[8];
#pragma unroll
            for (int r = 0; r < 8; ++r)   // rows rg + 8r (broadcast LDS.128)
                af[r] = *reinterpret_cast<const float4*>(&As[(rg + 8 * r) * K + k4]);
#pragma unroll
            for (int kk = 0; kk < 4; ++kk) {
                ulonglong2 wp[3];
#pragma unroll
                for (int gg = 0; gg < 3; ++gg)
                    wp[gg] = *reinterpret_cast<const ulonglong2*>(
                        &Ws[(size_t)(k4 + kk) * G_ + gg * H_ + 4 * cg]);
#pragma unroll
                for (int r = 0; r < 8; ++r) {
                    float a = (kk == 0) ? af[r].x : (kk == 1) ? af[r].y
                            : (kk == 2) ? af[r].z : af[r].w;
                    u64 ad = pk2(a, a);
#pragma unroll
                    for (int gg = 0; gg < 3; ++gg) {
                        fma2(acc[r][gg][0], ad, wp[gg].x);
                        fma2(acc[r][gg][1], ad, wp[gg].y);
                    }
                }
            }
        }

        // Interleaved store: row r = rg + 8r' -> b-lane = r'>>1, si = r'&1
        {
            const int bq = tile >> 6;
            const int s0 = (tile & 63) << 4;
#pragma unroll
            for (int si = 0; si < 2; ++si) {
                const int s = s0 + rg + 8 * si;
                float* Crow = g_xg + ((size_t)bq * S_ + s) * (G_ * 4);
#pragma unroll
                for (int gg = 0; gg < 3; ++gg) {
                    float q0[4], q1[4], q2[4], q3[4];
#pragma unroll
                    for (int b = 0; b < 4; ++b) {
                        upk2(acc[2 * b + si][gg][0], q0[b], q1[b]);
                        upk2(acc[2 * b + si][gg][1], q2[b], q3[b]);
                    }
                    float* p = Crow + (gg * H_ + 4 * cg) * 4;
                    *reinterpret_cast<float4*>(p)      = make_float4(
                        q0[0] + bv[gg].x, q0[1] + bv[gg].x, q0[2] + bv[gg].x, q0[3] + bv[gg].x);
                    *reinterpret_cast<float4*>(p + 4)  = make_float4(
                        q1[0] + bv[gg].y, q1[1] + bv[gg].y, q1[2] + bv[gg].y, q1[3] + bv[gg].y);
                    *reinterpret_cast<float4*>(p + 8)  = make_float4(
                        q2[0] + bv[gg].z, q2[1] + bv[gg].z, q2[2] + bv[gg].z, q2[3] + bv[gg].z);
                    *reinterpret_cast<float4*>(p + 12) = make_float4(
                        q3[0] + bv[gg].w, q3[1] + bv[gg].w, q3[2] + bv[gg].w, q3[3] + bv[gg].w);
                }
            }
        }
        __syncthreads();
    }
}

// ============================================================================
// Phase 2/4: recurrent scan. 128 CTAs x 4 batch rows, 384 threads.
// (identical to R8 — 1.82 ms/layer)
// ============================================================================
template<bool WRITE_ALL>
__global__ __launch_bounds__(384, 1) void gru_rec_kernel(
    const float* __restrict__ Whh, const float* __restrict__ bhh)
{
    __shared__ float h_s[4][H_];
    __shared__ float4 rbuf[H_];
    __shared__ float4 zbuf[H_];
    __shared__ float4 xstage[2][G_];

    const int g  = threadIdx.x;
    const int rb = blockIdx.x * 4;

    u64 wp[64];
    const u64* wrow = reinterpret_cast<const u64*>(Whh + (size_t)g * H_);
#pragma unroll
    for (int kk = 0; kk < 64; ++kk) wp[kk] = wrow[kk];
    const float bh = bhh[g];

    for (int idx = g; idx < 4 * H_; idx += 384)
        (&h_s[0][0])[idx] = 0.f;
    __syncthreads();

    const int sec = g >> 7;
    const int j   = g & 127;

    const float* xp = g_xg + (size_t)blockIdx.x * S_ * (G_ * 4) + g * 4;
    float* hall = g_h1 + ((size_t)rb * S_) * H_ + j;

    const uint32_t xs0 = smem_u32(&xstage[0][g]);
    const uint32_t xs1 = smem_u32(&xstage[1][g]);

    cp_async16(xs0, xp, 1);
    cp_commit();
    xp += G_ * 4;

    float hp0 = 0.f, hp1 = 0.f, hp2 = 0.f, hp3 = 0.f;

    const ulonglong2* hr0 = reinterpret_cast<const ulonglong2*>(h_s[0]);
    const ulonglong2* hr1 = reinterpret_cast<const ulonglong2*>(h_s[1]);
    const ulonglong2* hr2 = reinterpret_cast<const ulonglong2*>(h_s[2]);
    const ulonglong2* hr3 = reinterpret_cast<const ulonglong2*>(h_s[3]);

    for (int t = 0; t < S_; ++t) {
        cp_async16((t & 1) ? xs0 : xs1, xp, t + 1 < S_);
        cp_commit();
        xp += G_ * 4;

        u64 a0 = 0ull, a1 = 0ull, a2 = 0ull, a3 = 0ull;
#pragma unroll
        for (int kk = 0; kk < 32; ++kk) {
            ulonglong2 h0 = hr0[kk];
            ulonglong2 h1 = hr1[kk];
            ulonglong2 h2 = hr2[kk];
            ulonglong2 h3 = hr3[kk];
            u64 w0 = wp[2 * kk];
            u64 w1 = wp[2 * kk + 1];
            fma2(a0, h0.x, w0);
            fma2(a1, h1.x, w0);
            fma2(a2, h2.x, w0);
            fma2(a3, h3.x, w0);
            fma2(a0, h0.y, w1);
            fma2(a1, h1.y, w1);
            fma2(a2, h2.y, w1);
            fma2(a3, h3.y, w1);
        }
        float g0, g1, g2, g3, tlo, thi;
        upk2(a0, tlo, thi); g0 = tlo + thi + bh;
        upk2(a1, tlo, thi); g1 = tlo + thi + bh;
        upk2(a2, tlo, thi); g2 = tlo + thi + bh;
        upk2(a3, tlo, thi); g3 = tlo + thi + bh;

        cp_wait1();
        float4 xv = (t & 1) ? xstage[1][g] : xstage[0][g];

        if (sec == 0) {
            rbuf[j] = make_float4(sig_ap(xv.x + g0), sig_ap(xv.y + g1),
                                  sig_ap(xv.z + g2), sig_ap(xv.w + g3));
        } else if (sec == 1) {
            zbuf[j] = make_float4(sig_ap(xv.x + g0), sig_ap(xv.y + g1),
                                  sig_ap(xv.z + g2), sig_ap(xv.w + g3));
        }
        __syncthreads();
        if (sec == 2) {
            float4 rr = rbuf[j];
            float4 zz = zbuf[j];
            float n0 = tanh_ap(fmaf(rr.x, g0, xv.x));
            float n1 = tanh_ap(fmaf(rr.y, g1, xv.y));
            float n2 = tanh_ap(fmaf(rr.z, g2, xv.z));
            float n3 = tanh_ap(fmaf(rr.w, g3, xv.w));
            hp0 = fmaf(zz.x, hp0 - n0, n0);
            hp1 = fmaf(zz.y, hp1 - n1, n1);
            hp2 = fmaf(zz.z, hp2 - n2, n2);
            hp3 = fmaf(zz.w, hp3 - n3, n3);
            h_s[0][j] = hp0;
            h_s[1][j] = hp1;
            h_s[2][j] = hp2;
            h_s[3][j] = hp3;
            if (WRITE_ALL) {
                hall[0]                        = hp0;
                hall[(size_t)S_ * H_]          = hp1;
                hall[2 * (size_t)S_ * H_]      = hp2;
                hall[3 * (size_t)S_ * H_]      = hp3;
            } else if (t == S_ - 1) {
                g_h2last[(rb + 0) * H_ + j] = hp0;
                g_h2last[(rb + 1) * H_ + j] = hp1;
                g_h2last[(rb + 2) * H_ + j] = hp2;
                g_h2last[(rb + 3) * H_ + j] = hp3;
            }
        }
        __syncthreads();
        if (WRITE_ALL) hall += H_;
    }
}

// ============================================================================
// Phase 5: out[b][c] = h2last[b] . fc_w[c] + fc_b[c]
// ============================================================================
__global__ __launch_bounds__(128) void fc_kernel(
    const float* __restrict__ fw, const float* __restrict__ fb,
    float* __restrict__ out)
{
    __shared__ float sh[H_];
    const int b = blockIdx.x;
    sh[threadIdx.x] = g_h2last[b * H_ + threadIdx.x];
    __syncthreads();
    if (threadIdx.x < C_) {
        const int c = threadIdx.x;
        float acc = fb[c];
#pragma unroll
        for (int jj = 0; jj < H_; ++jj)
            acc += sh[jj] * fw[c * H_ + jj];
        out[b * C_ + c] = acc;
    }
}

extern "C" void kernel_launch(void* const* d_in, const int* in_sizes, int n_in,
                              void* d_out, int out_size)
{
    (void)in_sizes; (void)n_in; (void)out_size;
    const float* x      = (const float*)d_in[0];
    const float* W_ih0  = (const float*)d_in[1];
    const float* W_hh0  = (const float*)d_in[2];
    const float* b_ih0  = (const float*)d_in[3];
    const float* b_hh0  = (const float*)d_in[4];
    const float* W_ih1  = (const float*)d_in[5];
    const float* W_hh1  = (const float*)d_in[6];
    const float* b_ih1  = (const float*)d_in[7];
    const float* b_hh1  = (const float*)d_in[8];
    const float* fc_w   = (const float*)d_in[9];
    const float* fc_b   = (const float*)d_in[10];
    float* out = (float*)d_out;

    const int ntiles = (B_ / 4) * (S_ / 16);   // 8192
    const int smem64  = 64  * 4 * (G_ + 64);   // 114688 B
    const int smem128 = 128 * 4 * (G_ + 64);   // 229376 B

    cudaFuncSetAttribute(gemm_xg_kernel<64, false>,
                         cudaFuncAttributeMaxDynamicSharedMemorySize, smem64);
    cudaFuncSetAttribute(gemm_xg_kernel<128, true>,
                         cudaFuncAttributeMaxDynamicSharedMemorySize, smem128);

    // Layer 0
    gemm_xg_kernel<64, false><<<148, 256, smem64>>>(x, W_ih0, b_ih0, ntiles);
    gru_rec_kernel<true><<<128, 384>>>(W_hh0, b_hh0);
    // Layer 1
    gemm_xg_kernel<128, true><<<148, 256, smem128>>>(nullptr, W_ih1, b_ih1, ntiles);
    gru_rec_kernel<false><<<128, 384>>>(W_hh1, b_hh1);
    // Head
    fc_kernel<<<B_, 128>>>(fc_w, fc_b, out);
}